// round 8
// baseline (speedup 1.0000x reference)
#include <cuda_runtime.h>
#include <cuda_fp16.h>

// Weighted 4D LUT interpolation with 4x spatial upscale.
// Shapes: L=4, D=17, S=4, B=4, H=256, W=256, BINSIZE=16.
// lut:    [4,17,17,17,17,4,4] f32  (d_in[0])
// weight: [4,4,256,256]       f32  (d_in[2])
// x:      [4,1,256,256]       f32  (d_in[3])
// out:    [4,1,1024,1024]     f32
//
// fp16 LUT relayout g_lut2h[flat][s][l]: one 128B line per simplex vertex,
// s-major / l-minor (uint4 #j = s-pair {2j,2j+1} x 4 LUTs).
// Main kernel, 4 lanes/pixel: lane q loads uint4 #q and #(q+4) per vertex
// (same line, 10 hoisted LDG.128/thread), accumulates the 5-vertex k-sum
// IN FP16 with HFMA2 (1 instr per 2 LUT values), converts 8 half2 partials
// once, combines with weight[l] in fp32, stores its own 4 outputs. No
// shuffles. wts pre-packed to half2 and wg staged in smem by phase 1.

#define NPIX   (4 * 256 * 256)
#define D4     83521          // 17^4

// [flat][s][l] fp16: 64 halves = 128B per flat value = 8 uint4
__device__ uint4 g_lut2h[(size_t)D4 * 8];

__global__ void __launch_bounds__(256) relayout_kernel(const float* __restrict__ lut)
{
    int t = blockIdx.x * 256 + threadIdx.x;   // one dst uint4 per thread
    if (t >= D4 * 8) return;
    int j    = t & 7;          // s-pair index (s = 2j, 2j+1)
    int flat = t >> 3;

    float2 fl[4];
#pragma unroll
    for (int l = 0; l < 4; ++l)
        fl[l] = __ldg((const float2*)(lut + ((size_t)l * D4 + flat) * 16 + 2 * j));

    __half2 hh[4];
    hh[0] = __floats2half2_rn(fl[0].x, fl[1].x);   // s0: l0,l1
    hh[1] = __floats2half2_rn(fl[2].x, fl[3].x);   // s0: l2,l3
    hh[2] = __floats2half2_rn(fl[0].y, fl[1].y);   // s1: l0,l1
    hh[3] = __floats2half2_rn(fl[2].y, fl[3].y);   // s1: l2,l3

    g_lut2h[(size_t)flat * 8 + j] = *reinterpret_cast<uint4*>(hh);
}

__global__ void __launch_bounds__(256) w4dlut_kernel(
    const float* __restrict__ weight,
    const float* __restrict__ x,
    float* __restrict__ out)
{
    // per pixel: 5 x (flat, wts-as-half2) + weight[0..3]
    __shared__ uint2  s_fw[64][5];
    __shared__ float4 s_wg[64];

    int tid  = threadIdx.x;
    int pix0 = blockIdx.x * 64;

    // ---- phase 1: per-pixel setup, once (threads 0..63) ----
    if (tid < 64) {
        int g = pix0 + tid;
        int w = g & 255;
        int h = (g >> 8) & 255;
        int b = g >> 16;

        int h1 = (h + 1 < 256) ? h + 1 : 254;   // reflect pad
        int w1 = (w + 1 < 256) ? w + 1 : 254;

        const float* xb = x + b * 65536;
        float pv[4];
        pv[0] = xb[h  * 256 + w ];
        pv[1] = xb[h  * 256 + w1];
        pv[2] = xb[h1 * 256 + w ];
        pv[3] = xb[h1 * 256 + w1];

        float f[4];
        int   base[4];
#pragma unroll
        for (int d = 0; d < 4; ++d) {
            float tt = pv[d] * (1.0f / 16.0f);
            float bf = floorf(tt);
            f[d] = tt - bf;
            int bi = (int)bf;
            bi = min(max(bi, 0), 15);
            base[d] = bi;
        }

        // stable descending rank (matches jnp.argsort(-frac))
        int rank[4];
#pragma unroll
        for (int d = 0; d < 4; ++d) {
            int r = 0;
#pragma unroll
            for (int e = 0; e < 4; ++e)
                r += (f[e] > f[d]) || (f[e] == f[d] && e < d);
            rank[d] = r;
        }

        const int strides[4] = {4913, 289, 17, 1};
        float sf[4];
        int   sd[4];
#pragma unroll
        for (int r = 0; r < 4; ++r) {
            float v = 0.0f; int s = 0;
#pragma unroll
            for (int d = 0; d < 4; ++d)
                if (rank[d] == r) { v = f[d]; s = strides[d]; }
            sf[r] = v; sd[r] = s;
        }

        float wts[5];
        wts[0] = 1.0f - sf[0];
        wts[1] = sf[0] - sf[1];
        wts[2] = sf[1] - sf[2];
        wts[3] = sf[2] - sf[3];
        wts[4] = sf[3];

        int flat = ((base[0] * 17 + base[1]) * 17 + base[2]) * 17 + base[3];
#pragma unroll
        for (int k = 0; k < 5; ++k) {
            if (k) flat += sd[k - 1];
            __half2 wh = __float2half2_rn(wts[k]);
            s_fw[tid][k] = make_uint2((unsigned)flat,
                                      *reinterpret_cast<unsigned*>(&wh));
        }

        float4 wg4;
        wg4.x = weight[((b * 4 + 0) * 256 + h) * 256 + w];
        wg4.y = weight[((b * 4 + 1) * 256 + h) * 256 + w];
        wg4.z = weight[((b * 4 + 2) * 256 + h) * 256 + w];
        wg4.w = weight[((b * 4 + 3) * 256 + h) * 256 + w];
        s_wg[tid] = wg4;
    }
    __syncthreads();

    // ---- phase 2: cooperative gather, 4 lanes per pixel ----
    int q  = tid & 3;       // lane owns s {2q, 2q+1, 2q+8, 2q+9}
    int pl = tid >> 2;      // pixel slot in block (0..63)
    int g  = pix0 + pl;
    int w  = g & 255;
    int h  = (g >> 8) & 255;
    int b  = g >> 16;

    float4 wg = s_wg[pl];

    // hoist gathers: per vertex, uint4 #q and #(q+4) of the same 128B line
    uint4   v0[5], v1[5];
    __half2 cc[5];
#pragma unroll
    for (int k = 0; k < 5; ++k) {
        uint2 fw = s_fw[pl][k];
        cc[k] = *reinterpret_cast<__half2*>(&fw.y);
        const uint4* blk = g_lut2h + (size_t)fw.x * 8;
        v0[k] = __ldg(blk + q);
        v1[k] = __ldg(blk + q + 4);
    }

    // fp16 k-sum: acc[0..3] from v0 (s=2q, 2q+1), acc[4..7] from v1 (s=2q+8, 2q+9)
    __half2 acc[8];
#pragma unroll
    for (int i = 0; i < 8; ++i) acc[i] = __half2half2(__ushort_as_half(0));

#pragma unroll
    for (int k = 0; k < 5; ++k) {
        const __half2* ha = reinterpret_cast<const __half2*>(&v0[k]);
        const __half2* hb = reinterpret_cast<const __half2*>(&v1[k]);
        __half2 c = cc[k];
#pragma unroll
        for (int i = 0; i < 4; ++i) {
            acc[i]     = __hfma2(c, ha[i], acc[i]);
            acc[4 + i] = __hfma2(c, hb[i], acc[4 + i]);
        }
    }

    // fp32 epilogue: o[s-slot] = dot(acc_l01, wg01) + dot(acc_l23, wg23)
    float o[4];
#pragma unroll
    for (int i = 0; i < 4; ++i) {
        float2 f01 = __half22float2(acc[2 * i]);
        float2 f23 = __half22float2(acc[2 * i + 1]);
        float v = f01.x * wg.x;
        v = fmaf(f01.y, wg.y, v);
        v = fmaf(f23.x, wg.z, v);
        v = fmaf(f23.y, wg.w, v);
        o[i] = v;
    }

    // s=2q,2q+1 -> row sy=q>>1, col sx=2*(q&1); s=2q+8,2q+9 -> row sy+2
    int sy = q >> 1;
    int sx = 2 * (q & 1);
    size_t rbase = ((size_t)b * 1024 + h * 4 + sy) * 1024 + w * 4 + sx;
    *(float2*)(out + rbase)              = make_float2(o[0], o[1]);
    *(float2*)(out + rbase + 2 * 1024)   = make_float2(o[2], o[3]);
}

extern "C" void kernel_launch(void* const* d_in, const int* in_sizes, int n_in,
                              void* d_out, int out_size)
{
    const float* lut    = (const float*)d_in[0];
    const float* weight = (const float*)d_in[2];
    const float* x      = (const float*)d_in[3];
    float* out          = (float*)d_out;

    relayout_kernel<<<(D4 * 8 + 255) / 256, 256>>>(lut);
    w4dlut_kernel<<<NPIX / 64, 256>>>(weight, x, out);
}

// round 9
// speedup vs baseline: 1.0875x; 1.0875x over previous
#include <cuda_runtime.h>
#include <cuda_fp16.h>

// Weighted 4D LUT interpolation with 4x spatial upscale.
// Shapes: L=4, D=17, S=4, B=4, H=256, W=256, BINSIZE=16.
// lut:    [4,17,17,17,17,4,4] f32  (d_in[0])
// weight: [4,4,256,256]       f32  (d_in[2])
// x:      [4,1,256,256]       f32  (d_in[3])
// out:    [4,1,1024,1024]     f32
//
// fp16 LUT relayout g_lut2h[flat][s][l]: one 128B line per simplex vertex,
// s-major / l-minor (uint4 #m = halves 8m..8m+7, half index = s*4+l).
// Main kernel, 4 lanes/pixel with 256-bit gathers: lane q issues ONE
// LDG.256 per vertex covering its contiguous 32B quarter of the line
// (5 loads/thread; each warp instruction = 8 pixels x 1 full 128B line
// -> 5 L1 wavefronts/pixel). Lane q owns s = 4q..4q+3 = one output row:
// fp16 HFMA2 k-sum (8 half2 acc), fp32 weight-combine, one STG.128.

#define NPIX   (4 * 256 * 256)
#define D4     83521          // 17^4

// [flat][s][l] fp16: 64 halves = 128B per flat value = 8 uint4.
// 256B alignment so lane-level 32B vector loads are aligned.
__device__ __align__(256) uint4 g_lut2h[(size_t)D4 * 8];

__device__ __forceinline__ void ldg256(uint4& a, uint4& b, const void* p)
{
    asm("ld.global.nc.v8.b32 {%0,%1,%2,%3,%4,%5,%6,%7}, [%8];"
        : "=r"(a.x), "=r"(a.y), "=r"(a.z), "=r"(a.w),
          "=r"(b.x), "=r"(b.y), "=r"(b.z), "=r"(b.w)
        : "l"(p));
}

__global__ void __launch_bounds__(256) relayout_kernel(const float* __restrict__ lut)
{
    int t = blockIdx.x * 256 + threadIdx.x;   // one dst uint4 per thread
    if (t >= D4 * 8) return;
    int j    = t & 7;          // s-pair index (s = 2j, 2j+1)
    int flat = t >> 3;

    float2 fl[4];
#pragma unroll
    for (int l = 0; l < 4; ++l)
        fl[l] = __ldg((const float2*)(lut + ((size_t)l * D4 + flat) * 16 + 2 * j));

    __half2 hh[4];
    hh[0] = __floats2half2_rn(fl[0].x, fl[1].x);   // s(2j):   l0,l1
    hh[1] = __floats2half2_rn(fl[2].x, fl[3].x);   // s(2j):   l2,l3
    hh[2] = __floats2half2_rn(fl[0].y, fl[1].y);   // s(2j+1): l0,l1
    hh[3] = __floats2half2_rn(fl[2].y, fl[3].y);   // s(2j+1): l2,l3

    g_lut2h[(size_t)flat * 8 + j] = *reinterpret_cast<uint4*>(hh);
}

__global__ void __launch_bounds__(256) w4dlut_kernel(
    const float* __restrict__ weight,
    const float* __restrict__ x,
    float* __restrict__ out)
{
    // per pixel: 5 x (flat, wts-as-half2) + weight[0..3]
    __shared__ uint2  s_fw[64][5];
    __shared__ float4 s_wg[64];

    int tid  = threadIdx.x;
    int pix0 = blockIdx.x * 64;

    // ---- phase 1: per-pixel setup, once (threads 0..63) ----
    if (tid < 64) {
        int g = pix0 + tid;
        int w = g & 255;
        int h = (g >> 8) & 255;
        int b = g >> 16;

        int h1 = (h + 1 < 256) ? h + 1 : 254;   // reflect pad
        int w1 = (w + 1 < 256) ? w + 1 : 254;

        const float* xb = x + b * 65536;
        float pv[4];
        pv[0] = xb[h  * 256 + w ];
        pv[1] = xb[h  * 256 + w1];
        pv[2] = xb[h1 * 256 + w ];
        pv[3] = xb[h1 * 256 + w1];

        float f[4];
        int   base[4];
#pragma unroll
        for (int d = 0; d < 4; ++d) {
            float tt = pv[d] * (1.0f / 16.0f);
            float bf = floorf(tt);
            f[d] = tt - bf;
            int bi = (int)bf;
            bi = min(max(bi, 0), 15);
            base[d] = bi;
        }

        // stable descending rank (matches jnp.argsort(-frac))
        int rank[4];
#pragma unroll
        for (int d = 0; d < 4; ++d) {
            int r = 0;
#pragma unroll
            for (int e = 0; e < 4; ++e)
                r += (f[e] > f[d]) || (f[e] == f[d] && e < d);
            rank[d] = r;
        }

        const int strides[4] = {4913, 289, 17, 1};
        float sf[4];
        int   sd[4];
#pragma unroll
        for (int r = 0; r < 4; ++r) {
            float v = 0.0f; int s = 0;
#pragma unroll
            for (int d = 0; d < 4; ++d)
                if (rank[d] == r) { v = f[d]; s = strides[d]; }
            sf[r] = v; sd[r] = s;
        }

        float wts[5];
        wts[0] = 1.0f - sf[0];
        wts[1] = sf[0] - sf[1];
        wts[2] = sf[1] - sf[2];
        wts[3] = sf[2] - sf[3];
        wts[4] = sf[3];

        int flat = ((base[0] * 17 + base[1]) * 17 + base[2]) * 17 + base[3];
#pragma unroll
        for (int k = 0; k < 5; ++k) {
            if (k) flat += sd[k - 1];
            __half2 wh = __float2half2_rn(wts[k]);
            s_fw[tid][k] = make_uint2((unsigned)flat,
                                      *reinterpret_cast<unsigned*>(&wh));
        }

        float4 wg4;
        wg4.x = weight[((b * 4 + 0) * 256 + h) * 256 + w];
        wg4.y = weight[((b * 4 + 1) * 256 + h) * 256 + w];
        wg4.z = weight[((b * 4 + 2) * 256 + h) * 256 + w];
        wg4.w = weight[((b * 4 + 3) * 256 + h) * 256 + w];
        s_wg[tid] = wg4;
    }
    __syncthreads();

    // ---- phase 2: cooperative gather, 4 lanes per pixel, LDG.256 ----
    int q  = tid & 3;       // lane owns s = 4q..4q+3  (output row sy=q)
    int pl = tid >> 2;      // pixel slot in block (0..63)
    int g  = pix0 + pl;
    int w  = g & 255;
    int h  = (g >> 8) & 255;
    int b  = g >> 16;

    float4 wg = s_wg[pl];

    // hoist gathers: one 32B vector load per vertex (contiguous quarter)
    uint4   v0[5], v1[5];
    __half2 cc[5];
#pragma unroll
    for (int k = 0; k < 5; ++k) {
        uint2 fw = s_fw[pl][k];
        cc[k] = *reinterpret_cast<__half2*>(&fw.y);
        const char* p = (const char*)g_lut2h + ((size_t)fw.x * 128 + q * 32);
        ldg256(v0[k], v1[k], p);
    }

    // fp16 k-sum over 5 vertices: 16 halves = 8 half2 accumulators
    // half i pair layout: (s_local, l): h[0]=(s0 l01) h[1]=(s0 l23)
    //                     h[2]=(s1 l01) ... h[7]=(s3 l23), s_local = 0..3
    __half2 acc[8];
#pragma unroll
    for (int i = 0; i < 8; ++i) acc[i] = __half2half2(__ushort_as_half(0));

#pragma unroll
    for (int k = 0; k < 5; ++k) {
        const __half2* ha = reinterpret_cast<const __half2*>(&v0[k]);
        const __half2* hb = reinterpret_cast<const __half2*>(&v1[k]);
        __half2 c = cc[k];
#pragma unroll
        for (int i = 0; i < 4; ++i) {
            acc[i]     = __hfma2(c, ha[i], acc[i]);
            acc[4 + i] = __hfma2(c, hb[i], acc[4 + i]);
        }
    }

    // fp32 epilogue: o[s_local] = dot over l with weight
    float o[4];
#pragma unroll
    for (int i = 0; i < 4; ++i) {
        float2 f01 = __half22float2(acc[2 * i]);
        float2 f23 = __half22float2(acc[2 * i + 1]);
        float v = f01.x * wg.x;
        v = fmaf(f01.y, wg.y, v);
        v = fmaf(f23.x, wg.z, v);
        v = fmaf(f23.y, wg.w, v);
        o[i] = v;
    }

    // lane q writes out[b, 0, h*4+q, w*4 .. w*4+3]  (one STG.128)
    float4* op = (float4*)(out + (((size_t)b * 1024 + h * 4 + q) * 1024 + w * 4));
    *op = make_float4(o[0], o[1], o[2], o[3]);
}

extern "C" void kernel_launch(void* const* d_in, const int* in_sizes, int n_in,
                              void* d_out, int out_size)
{
    const float* lut    = (const float*)d_in[0];
    const float* weight = (const float*)d_in[2];
    const float* x      = (const float*)d_in[3];
    float* out          = (float*)d_out;

    relayout_kernel<<<(D4 * 8 + 255) / 256, 256>>>(lut);
    w4dlut_kernel<<<NPIX / 64, 256>>>(weight, x, out);
}

// round 10
// speedup vs baseline: 1.1008x; 1.0122x over previous
#include <cuda_runtime.h>
#include <cuda_fp16.h>

// Weighted 4D LUT interpolation with 4x spatial upscale.
// Shapes: L=4, D=17, S=4, B=4, H=256, W=256, BINSIZE=16.
// lut:    [4,17,17,17,17,4,4] f32  (d_in[0])
// weight: [4,4,256,256]       f32  (d_in[2])
// x:      [4,1,256,256]       f32  (d_in[3])
// out:    [4,1,1024,1024]     f32
//
// fp16 LUT relayout g_lut2h[flat][s][l]: one 128B line per simplex vertex,
// s-major / l-minor (uint4 #m = halves 8m..8m+7, half index = s*4+l).
// Main kernel, 4 lanes/pixel with 256-bit gathers: lane q issues ONE
// LDG.256 per vertex covering its contiguous 32B quarter of the line
// (5 loads/thread; each warp instruction = 8 pixels x 1 full 128B line
// -> 5 L1 wavefronts/pixel). Lane q owns s = 4q..4q+3 = one output row:
// fp16 HFMA2 k-sum (8 half2 acc), fp32 weight-combine, one STG.128.

#define NPIX   (4 * 256 * 256)
#define D4     83521          // 17^4

// [flat][s][l] fp16: 64 halves = 128B per flat value = 8 uint4.
// 256B alignment so lane-level 32B vector loads are aligned.
__device__ __align__(256) uint4 g_lut2h[(size_t)D4 * 8];

__device__ __forceinline__ void ldg256(uint4& a, uint4& b, const void* p)
{
    asm("ld.global.nc.v8.b32 {%0,%1,%2,%3,%4,%5,%6,%7}, [%8];"
        : "=r"(a.x), "=r"(a.y), "=r"(a.z), "=r"(a.w),
          "=r"(b.x), "=r"(b.y), "=r"(b.z), "=r"(b.w)
        : "l"(p));
}

__global__ void __launch_bounds__(256) relayout_kernel(const float* __restrict__ lut)
{
    int t = blockIdx.x * 256 + threadIdx.x;   // one dst uint4 per thread
    if (t >= D4 * 8) return;
    int j    = t & 7;          // s-pair index (s = 2j, 2j+1)
    int flat = t >> 3;

    float2 fl[4];
#pragma unroll
    for (int l = 0; l < 4; ++l)
        fl[l] = __ldg((const float2*)(lut + ((size_t)l * D4 + flat) * 16 + 2 * j));

    __half2 hh[4];
    hh[0] = __floats2half2_rn(fl[0].x, fl[1].x);   // s(2j):   l0,l1
    hh[1] = __floats2half2_rn(fl[2].x, fl[3].x);   // s(2j):   l2,l3
    hh[2] = __floats2half2_rn(fl[0].y, fl[1].y);   // s(2j+1): l0,l1
    hh[3] = __floats2half2_rn(fl[2].y, fl[3].y);   // s(2j+1): l2,l3

    g_lut2h[(size_t)flat * 8 + j] = *reinterpret_cast<uint4*>(hh);
}

__global__ void __launch_bounds__(256) w4dlut_kernel(
    const float* __restrict__ weight,
    const float* __restrict__ x,
    float* __restrict__ out)
{
    // per pixel: 5 x (flat, wts-as-half2) + weight[0..3]
    __shared__ uint2  s_fw[64][5];
    __shared__ float4 s_wg[64];

    int tid  = threadIdx.x;
    int pix0 = blockIdx.x * 64;

    // ---- phase 1: per-pixel setup, once (threads 0..63) ----
    if (tid < 64) {
        int g = pix0 + tid;
        int w = g & 255;
        int h = (g >> 8) & 255;
        int b = g >> 16;

        int h1 = (h + 1 < 256) ? h + 1 : 254;   // reflect pad
        int w1 = (w + 1 < 256) ? w + 1 : 254;

        const float* xb = x + b * 65536;
        float pv[4];
        pv[0] = xb[h  * 256 + w ];
        pv[1] = xb[h  * 256 + w1];
        pv[2] = xb[h1 * 256 + w ];
        pv[3] = xb[h1 * 256 + w1];

        float f[4];
        int   base[4];
#pragma unroll
        for (int d = 0; d < 4; ++d) {
            float tt = pv[d] * (1.0f / 16.0f);
            float bf = floorf(tt);
            f[d] = tt - bf;
            int bi = (int)bf;
            bi = min(max(bi, 0), 15);
            base[d] = bi;
        }

        // stable descending rank (matches jnp.argsort(-frac))
        int rank[4];
#pragma unroll
        for (int d = 0; d < 4; ++d) {
            int r = 0;
#pragma unroll
            for (int e = 0; e < 4; ++e)
                r += (f[e] > f[d]) || (f[e] == f[d] && e < d);
            rank[d] = r;
        }

        const int strides[4] = {4913, 289, 17, 1};
        float sf[4];
        int   sd[4];
#pragma unroll
        for (int r = 0; r < 4; ++r) {
            float v = 0.0f; int s = 0;
#pragma unroll
            for (int d = 0; d < 4; ++d)
                if (rank[d] == r) { v = f[d]; s = strides[d]; }
            sf[r] = v; sd[r] = s;
        }

        float wts[5];
        wts[0] = 1.0f - sf[0];
        wts[1] = sf[0] - sf[1];
        wts[2] = sf[1] - sf[2];
        wts[3] = sf[2] - sf[3];
        wts[4] = sf[3];

        int flat = ((base[0] * 17 + base[1]) * 17 + base[2]) * 17 + base[3];
#pragma unroll
        for (int k = 0; k < 5; ++k) {
            if (k) flat += sd[k - 1];
            __half2 wh = __float2half2_rn(wts[k]);
            s_fw[tid][k] = make_uint2((unsigned)flat,
                                      *reinterpret_cast<unsigned*>(&wh));
        }

        float4 wg4;
        wg4.x = weight[((b * 4 + 0) * 256 + h) * 256 + w];
        wg4.y = weight[((b * 4 + 1) * 256 + h) * 256 + w];
        wg4.z = weight[((b * 4 + 2) * 256 + h) * 256 + w];
        wg4.w = weight[((b * 4 + 3) * 256 + h) * 256 + w];
        s_wg[tid] = wg4;
    }
    __syncthreads();

    // ---- phase 2: cooperative gather, 4 lanes per pixel, LDG.256 ----
    int q  = tid & 3;       // lane owns s = 4q..4q+3  (output row sy=q)
    int pl = tid >> 2;      // pixel slot in block (0..63)
    int g  = pix0 + pl;
    int w  = g & 255;
    int h  = (g >> 8) & 255;
    int b  = g >> 16;

    float4 wg = s_wg[pl];

    // hoist gathers: one 32B vector load per vertex (contiguous quarter)
    uint4   v0[5], v1[5];
    __half2 cc[5];
#pragma unroll
    for (int k = 0; k < 5; ++k) {
        uint2 fw = s_fw[pl][k];
        cc[k] = *reinterpret_cast<__half2*>(&fw.y);
        const char* p = (const char*)g_lut2h + ((size_t)fw.x * 128 + q * 32);
        ldg256(v0[k], v1[k], p);
    }

    // fp16 k-sum over 5 vertices: 16 halves = 8 half2 accumulators
    // half i pair layout: (s_local, l): h[0]=(s0 l01) h[1]=(s0 l23)
    //                     h[2]=(s1 l01) ... h[7]=(s3 l23), s_local = 0..3
    __half2 acc[8];
#pragma unroll
    for (int i = 0; i < 8; ++i) acc[i] = __half2half2(__ushort_as_half(0));

#pragma unroll
    for (int k = 0; k < 5; ++k) {
        const __half2* ha = reinterpret_cast<const __half2*>(&v0[k]);
        const __half2* hb = reinterpret_cast<const __half2*>(&v1[k]);
        __half2 c = cc[k];
#pragma unroll
        for (int i = 0; i < 4; ++i) {
            acc[i]     = __hfma2(c, ha[i], acc[i]);
            acc[4 + i] = __hfma2(c, hb[i], acc[4 + i]);
        }
    }

    // fp32 epilogue: o[s_local] = dot over l with weight
    float o[4];
#pragma unroll
    for (int i = 0; i < 4; ++i) {
        float2 f01 = __half22float2(acc[2 * i]);
        float2 f23 = __half22float2(acc[2 * i + 1]);
        float v = f01.x * wg.x;
        v = fmaf(f01.y, wg.y, v);
        v = fmaf(f23.x, wg.z, v);
        v = fmaf(f23.y, wg.w, v);
        o[i] = v;
    }

    // lane q writes out[b, 0, h*4+q, w*4 .. w*4+3]  (one STG.128)
    float4* op = (float4*)(out + (((size_t)b * 1024 + h * 4 + q) * 1024 + w * 4));
    *op = make_float4(o[0], o[1], o[2], o[3]);
}

extern "C" void kernel_launch(void* const* d_in, const int* in_sizes, int n_in,
                              void* d_out, int out_size)
{
    const float* lut    = (const float*)d_in[0];
    const float* weight = (const float*)d_in[2];
    const float* x      = (const float*)d_in[3];
    float* out          = (float*)d_out;

    relayout_kernel<<<(D4 * 8 + 255) / 256, 256>>>(lut);
    w4dlut_kernel<<<NPIX / 64, 256>>>(weight, x, out);
}